// round 13
// baseline (speedup 1.0000x reference)
#include <cuda_runtime.h>

// Fixed problem shape (from reference): N = 100,000 nodes.
#define MAX_NODES 100000

// Combined scratch table: [0, N) = out-degree (by src), [N, 2N) = in-degree
// (by dst). Later overwritten in-place with rsqrt(deg).
__device__ float g_norm[2 * MAX_NODES];

// ---------------------------------------------------------------------------
// Kernel 1: zero the accumulators, float4-vectorized. Device globals persist
// across graph replays, so they MUST be re-zeroed on every launch.
// ---------------------------------------------------------------------------
__global__ void zero_deg_kernel() {
    int i = blockIdx.x * blockDim.x + threadIdx.x;
    if (i < (2 * MAX_NODES) / 4) {
        ((float4*)g_norm)[i] = make_float4(0.f, 0.f, 0.f, 0.f);
    }
}

// ---------------------------------------------------------------------------
// Kernel 2: scatter edge weights into out-degree (by src) and in-degree (by
// dst). 4 edges per thread via float4/int4 loads — measured-best config.
// atomicAdd with unused return -> REDG (no round trip). Bound by the
// spread-address REDG dispatch floor (~1.3 cyc/lane/SM); ILP- and
// block-size-invariant (verified R4/R6).
// ---------------------------------------------------------------------------
__global__ void __launch_bounds__(256)
scatter_deg_kernel(const float4* __restrict__ w4,
                   const int4*   __restrict__ s4,
                   const int4*   __restrict__ d4,
                   int n4) {
    int tid = blockIdx.x * blockDim.x + threadIdx.x;
    if (tid >= n4) return;
    int4   sv = s4[tid];
    int4   dv = d4[tid];
    float4 wv = w4[tid];
    atomicAdd(&g_norm[sv.x], wv.x);
    atomicAdd(&g_norm[sv.y], wv.y);
    atomicAdd(&g_norm[sv.z], wv.z);
    atomicAdd(&g_norm[sv.w], wv.w);
    atomicAdd(&g_norm[MAX_NODES + dv.x], wv.x);
    atomicAdd(&g_norm[MAX_NODES + dv.y], wv.y);
    atomicAdd(&g_norm[MAX_NODES + dv.z], wv.z);
    atomicAdd(&g_norm[MAX_NODES + dv.w], wv.w);
}

// Scalar tail for generality (launched only when E % 4 != 0).
__global__ void scatter_tail_kernel(const float* __restrict__ w,
                                    const int*   __restrict__ s,
                                    const int*   __restrict__ d,
                                    int start, int E) {
    int i = start + blockIdx.x * blockDim.x + threadIdx.x;
    if (i < E) {
        float wv = w[i];
        atomicAdd(&g_norm[s[i]], wv);
        atomicAdd(&g_norm[MAX_NODES + d[i]], wv);
    }
}

// ---------------------------------------------------------------------------
// Kernel 3: per-node rsqrt, in place, float4-vectorized over the combined
// table. deg==0 -> +inf, but such nodes never appear on the corresponding
// side of any edge, so the inf is never gathered.
// ---------------------------------------------------------------------------
__global__ void rsqrt_deg_kernel() {
    int i = blockIdx.x * blockDim.x + threadIdx.x;
    if (i < (2 * MAX_NODES) / 4) {
        float4 v = ((float4*)g_norm)[i];
        v.x = rsqrtf(v.x);
        v.y = rsqrtf(v.y);
        v.z = rsqrtf(v.z);
        v.w = rsqrtf(v.w);
        ((float4*)g_norm)[i] = v;
    }
}

// ---------------------------------------------------------------------------
// Kernel 4: per-edge gather-multiply. Measured-best config (174.5us):
// 4 edges per thread, TPB=256, indices loaded first, 8 random gathers
// front-batched for deep MLP. L1tex-wavefront bound at ~90% of peak
// (architectural floor: 1 wavefront per random 4B lane).
// ---------------------------------------------------------------------------
__global__ void __launch_bounds__(256)
gather_mul_kernel(const float4* __restrict__ w4,
                  const int4*   __restrict__ s4,
                  const int4*   __restrict__ d4,
                  float4* __restrict__ out4,
                  int n4) {
    int tid = blockIdx.x * blockDim.x + threadIdx.x;
    if (tid >= n4) return;
    int4   sv = s4[tid];
    int4   dv = d4[tid];
    float4 wv = w4[tid];
    // Front-batch all 8 random gathers.
    float sx = g_norm[sv.x], sy = g_norm[sv.y];
    float sz = g_norm[sv.z], sw = g_norm[sv.w];
    float dx = g_norm[MAX_NODES + dv.x], dy = g_norm[MAX_NODES + dv.y];
    float dz = g_norm[MAX_NODES + dv.z], dw = g_norm[MAX_NODES + dv.w];
    float4 r;
    r.x = sx * dx * wv.x;
    r.y = sy * dy * wv.y;
    r.z = sz * dz * wv.z;
    r.w = sw * dw * wv.w;
    out4[tid] = r;
}

// Scalar tail for generality (launched only when E % 4 != 0).
__global__ void gather_tail_kernel(const float* __restrict__ w,
                                   const int*   __restrict__ s,
                                   const int*   __restrict__ d,
                                   float* __restrict__ out,
                                   int start, int E) {
    int i = start + blockIdx.x * blockDim.x + threadIdx.x;
    if (i < E) {
        out[i] = g_norm[s[i]] * g_norm[MAX_NODES + d[i]] * w[i];
    }
}

extern "C" void kernel_launch(void* const* d_in, const int* in_sizes, int n_in,
                              void* d_out, int out_size) {
    const float* w   = (const float*)d_in[0];
    const int*   src = (const int*)d_in[1];
    const int*   dst = (const int*)d_in[2];
    float* out = (float*)d_out;

    int E    = in_sizes[0];
    int n4   = E / 4;
    int tail = E - 4 * n4;

    const int TPB = 256;
    const int NV4 = (2 * MAX_NODES) / 4;  // 100,000 float4s

    zero_deg_kernel<<<(NV4 + TPB - 1) / TPB, TPB>>>();

    scatter_deg_kernel<<<(n4 + TPB - 1) / TPB, TPB>>>(
        (const float4*)w, (const int4*)src, (const int4*)dst, n4);
    if (tail > 0) {
        scatter_tail_kernel<<<1, TPB>>>(w, src, dst, 4 * n4, E);
    }

    rsqrt_deg_kernel<<<(NV4 + TPB - 1) / TPB, TPB>>>();

    gather_mul_kernel<<<(n4 + TPB - 1) / TPB, TPB>>>(
        (const float4*)w, (const int4*)src, (const int4*)dst,
        (float4*)out, n4);
    if (tail > 0) {
        gather_tail_kernel<<<1, TPB>>>(w, src, dst, out, 4 * n4, E);
    }
}

// round 14
// speedup vs baseline: 1.3679x; 1.3679x over previous
#include <cuda_runtime.h>

// Fixed problem shape (from reference): N = 100,000 nodes.
#define MAX_NODES 100000

// Combined scratch table: [0, N) = out-degree (by src), [N, 2N) = in-degree
// (by dst). Later overwritten in-place with rsqrt(deg).
__device__ float g_norm[2 * MAX_NODES];

// ---------------------------------------------------------------------------
// Kernel 1: zero the accumulators, float4-vectorized. Device globals persist
// across graph replays, so they MUST be re-zeroed on every launch.
// ---------------------------------------------------------------------------
__global__ void zero_deg_kernel() {
    int i = blockIdx.x * blockDim.x + threadIdx.x;
    if (i < (2 * MAX_NODES) / 4) {
        ((float4*)g_norm)[i] = make_float4(0.f, 0.f, 0.f, 0.f);
    }
}

// ---------------------------------------------------------------------------
// Kernel 2: scatter edge weights into out-degree (by src) and in-degree (by
// dst). 4 edges per thread via float4/int4 loads — measured-best config.
// atomicAdd with unused return -> REDG (no round trip). Bound by the
// spread-address REDG dispatch floor (~1.3 cyc/lane/SM); ILP- and
// block-size-invariant (verified R4/R6).
// ---------------------------------------------------------------------------
__global__ void __launch_bounds__(256)
scatter_deg_kernel(const float4* __restrict__ w4,
                   const int4*   __restrict__ s4,
                   const int4*   __restrict__ d4,
                   int n4) {
    int tid = blockIdx.x * blockDim.x + threadIdx.x;
    if (tid >= n4) return;
    int4   sv = s4[tid];
    int4   dv = d4[tid];
    float4 wv = w4[tid];
    atomicAdd(&g_norm[sv.x], wv.x);
    atomicAdd(&g_norm[sv.y], wv.y);
    atomicAdd(&g_norm[sv.z], wv.z);
    atomicAdd(&g_norm[sv.w], wv.w);
    atomicAdd(&g_norm[MAX_NODES + dv.x], wv.x);
    atomicAdd(&g_norm[MAX_NODES + dv.y], wv.y);
    atomicAdd(&g_norm[MAX_NODES + dv.z], wv.z);
    atomicAdd(&g_norm[MAX_NODES + dv.w], wv.w);
}

// Scalar tail for generality (launched only when E % 4 != 0).
__global__ void scatter_tail_kernel(const float* __restrict__ w,
                                    const int*   __restrict__ s,
                                    const int*   __restrict__ d,
                                    int start, int E) {
    int i = start + blockIdx.x * blockDim.x + threadIdx.x;
    if (i < E) {
        float wv = w[i];
        atomicAdd(&g_norm[s[i]], wv);
        atomicAdd(&g_norm[MAX_NODES + d[i]], wv);
    }
}

// ---------------------------------------------------------------------------
// Kernel 3: per-node rsqrt, in place, float4-vectorized over the combined
// table. deg==0 -> +inf, but such nodes never appear on the corresponding
// side of any edge, so the inf is never gathered.
// ---------------------------------------------------------------------------
__global__ void rsqrt_deg_kernel() {
    int i = blockIdx.x * blockDim.x + threadIdx.x;
    if (i < (2 * MAX_NODES) / 4) {
        float4 v = ((float4*)g_norm)[i];
        v.x = rsqrtf(v.x);
        v.y = rsqrtf(v.y);
        v.z = rsqrtf(v.z);
        v.w = rsqrtf(v.w);
        ((float4*)g_norm)[i] = v;
    }
}

// ---------------------------------------------------------------------------
// Kernel 4: per-edge gather-multiply. Measured-best config (174.5us at full
// clock): 4 edges per thread, TPB=256, indices loaded first, 8 random
// gathers front-batched for deep MLP. L1tex-wavefront bound at ~90% of peak
// (architectural floor: 1 wavefront per random 4B lane).
// ---------------------------------------------------------------------------
__global__ void __launch_bounds__(256)
gather_mul_kernel(const float4* __restrict__ w4,
                  const int4*   __restrict__ s4,
                  const int4*   __restrict__ d4,
                  float4* __restrict__ out4,
                  int n4) {
    int tid = blockIdx.x * blockDim.x + threadIdx.x;
    if (tid >= n4) return;
    int4   sv = s4[tid];
    int4   dv = d4[tid];
    float4 wv = w4[tid];
    // Front-batch all 8 random gathers.
    float sx = g_norm[sv.x], sy = g_norm[sv.y];
    float sz = g_norm[sv.z], sw = g_norm[sv.w];
    float dx = g_norm[MAX_NODES + dv.x], dy = g_norm[MAX_NODES + dv.y];
    float dz = g_norm[MAX_NODES + dv.z], dw = g_norm[MAX_NODES + dv.w];
    float4 r;
    r.x = sx * dx * wv.x;
    r.y = sy * dy * wv.y;
    r.z = sz * dz * wv.z;
    r.w = sw * dw * wv.w;
    out4[tid] = r;
}

// Scalar tail for generality (launched only when E % 4 != 0).
__global__ void gather_tail_kernel(const float* __restrict__ w,
                                   const int*   __restrict__ s,
                                   const int*   __restrict__ d,
                                   float* __restrict__ out,
                                   int start, int E) {
    int i = start + blockIdx.x * blockDim.x + threadIdx.x;
    if (i < E) {
        out[i] = g_norm[s[i]] * g_norm[MAX_NODES + d[i]] * w[i];
    }
}

extern "C" void kernel_launch(void* const* d_in, const int* in_sizes, int n_in,
                              void* d_out, int out_size) {
    const float* w   = (const float*)d_in[0];
    const int*   src = (const int*)d_in[1];
    const int*   dst = (const int*)d_in[2];
    float* out = (float*)d_out;

    int E    = in_sizes[0];
    int n4   = E / 4;
    int tail = E - 4 * n4;

    const int TPB = 256;
    const int NV4 = (2 * MAX_NODES) / 4;  // 100,000 float4s

    zero_deg_kernel<<<(NV4 + TPB - 1) / TPB, TPB>>>();

    scatter_deg_kernel<<<(n4 + TPB - 1) / TPB, TPB>>>(
        (const float4*)w, (const int4*)src, (const int4*)dst, n4);
    if (tail > 0) {
        scatter_tail_kernel<<<1, TPB>>>(w, src, dst, 4 * n4, E);
    }

    rsqrt_deg_kernel<<<(NV4 + TPB - 1) / TPB, TPB>>>();

    gather_mul_kernel<<<(n4 + TPB - 1) / TPB, TPB>>>(
        (const float4*)w, (const int4*)src, (const int4*)dst,
        (float4*)out, n4);
    if (tail > 0) {
        gather_tail_kernel<<<1, TPB>>>(w, src, dst, out, 4 * n4, E);
    }
}

// round 16
// speedup vs baseline: 1.3736x; 1.0042x over previous
#include <cuda_runtime.h>

// Fixed problem shape (from reference): N = 100,000 nodes.
#define MAX_NODES 100000

// Combined scratch table: [0, N) = out-degree (by src), [N, 2N) = in-degree
// (by dst). Later overwritten in-place with rsqrt(deg).
__device__ float g_norm[2 * MAX_NODES];

// ---------------------------------------------------------------------------
// Kernel 1: zero the accumulators, float4-vectorized. Device globals persist
// across graph replays, so they MUST be re-zeroed on every launch.
// ---------------------------------------------------------------------------
__global__ void zero_deg_kernel() {
    int i = blockIdx.x * blockDim.x + threadIdx.x;
    if (i < (2 * MAX_NODES) / 4) {
        ((float4*)g_norm)[i] = make_float4(0.f, 0.f, 0.f, 0.f);
    }
}

// ---------------------------------------------------------------------------
// Kernel 2: scatter edge weights into out-degree (by src) and in-degree (by
// dst). 4 edges per thread via float4/int4 loads — measured-best config.
// atomicAdd with unused return -> REDG (no round trip). Bound by the
// spread-address REDG dispatch floor (~1.3 cyc/lane/SM); ILP- and
// block-size-invariant (verified R4/R6).
// ---------------------------------------------------------------------------
__global__ void __launch_bounds__(256)
scatter_deg_kernel(const float4* __restrict__ w4,
                   const int4*   __restrict__ s4,
                   const int4*   __restrict__ d4,
                   int n4) {
    int tid = blockIdx.x * blockDim.x + threadIdx.x;
    if (tid >= n4) return;
    int4   sv = s4[tid];
    int4   dv = d4[tid];
    float4 wv = w4[tid];
    atomicAdd(&g_norm[sv.x], wv.x);
    atomicAdd(&g_norm[sv.y], wv.y);
    atomicAdd(&g_norm[sv.z], wv.z);
    atomicAdd(&g_norm[sv.w], wv.w);
    atomicAdd(&g_norm[MAX_NODES + dv.x], wv.x);
    atomicAdd(&g_norm[MAX_NODES + dv.y], wv.y);
    atomicAdd(&g_norm[MAX_NODES + dv.z], wv.z);
    atomicAdd(&g_norm[MAX_NODES + dv.w], wv.w);
}

// Scalar tail for generality (launched only when E % 4 != 0).
__global__ void scatter_tail_kernel(const float* __restrict__ w,
                                    const int*   __restrict__ s,
                                    const int*   __restrict__ d,
                                    int start, int E) {
    int i = start + blockIdx.x * blockDim.x + threadIdx.x;
    if (i < E) {
        float wv = w[i];
        atomicAdd(&g_norm[s[i]], wv);
        atomicAdd(&g_norm[MAX_NODES + d[i]], wv);
    }
}

// ---------------------------------------------------------------------------
// Kernel 3: per-node rsqrt, in place, float4-vectorized over the combined
// table. deg==0 -> +inf, but such nodes never appear on the corresponding
// side of any edge, so the inf is never gathered.
// ---------------------------------------------------------------------------
__global__ void rsqrt_deg_kernel() {
    int i = blockIdx.x * blockDim.x + threadIdx.x;
    if (i < (2 * MAX_NODES) / 4) {
        float4 v = ((float4*)g_norm)[i];
        v.x = rsqrtf(v.x);
        v.y = rsqrtf(v.y);
        v.z = rsqrtf(v.z);
        v.w = rsqrtf(v.w);
        ((float4*)g_norm)[i] = v;
    }
}

// ---------------------------------------------------------------------------
// Kernel 4: per-edge gather-multiply. Same per-thread body as the 434.2us
// winner (4 edges/thread, indices first, 8 random gathers front-batched;
// L1tex-wavefront bound at ~90% of peak). Single-variable test: TPB=512
// (halves block count; regs=32 so occupancy unchanged).
// ---------------------------------------------------------------------------
__global__ void __launch_bounds__(512)
gather_mul_kernel(const float4* __restrict__ w4,
                  const int4*   __restrict__ s4,
                  const int4*   __restrict__ d4,
                  float4* __restrict__ out4,
                  int n4) {
    int tid = blockIdx.x * blockDim.x + threadIdx.x;
    if (tid >= n4) return;
    int4   sv = s4[tid];
    int4   dv = d4[tid];
    float4 wv = w4[tid];
    // Front-batch all 8 random gathers.
    float sx = g_norm[sv.x], sy = g_norm[sv.y];
    float sz = g_norm[sv.z], sw = g_norm[sv.w];
    float dx = g_norm[MAX_NODES + dv.x], dy = g_norm[MAX_NODES + dv.y];
    float dz = g_norm[MAX_NODES + dv.z], dw = g_norm[MAX_NODES + dv.w];
    float4 r;
    r.x = sx * dx * wv.x;
    r.y = sy * dy * wv.y;
    r.z = sz * dz * wv.z;
    r.w = sw * dw * wv.w;
    out4[tid] = r;
}

// Scalar tail for generality (launched only when E % 4 != 0).
__global__ void gather_tail_kernel(const float* __restrict__ w,
                                   const int*   __restrict__ s,
                                   const int*   __restrict__ d,
                                   float* __restrict__ out,
                                   int start, int E) {
    int i = start + blockIdx.x * blockDim.x + threadIdx.x;
    if (i < E) {
        out[i] = g_norm[s[i]] * g_norm[MAX_NODES + d[i]] * w[i];
    }
}

extern "C" void kernel_launch(void* const* d_in, const int* in_sizes, int n_in,
                              void* d_out, int out_size) {
    const float* w   = (const float*)d_in[0];
    const int*   src = (const int*)d_in[1];
    const int*   dst = (const int*)d_in[2];
    float* out = (float*)d_out;

    int E    = in_sizes[0];
    int n4   = E / 4;
    int tail = E - 4 * n4;

    const int TPB = 256;
    const int G_TPB = 512;
    const int NV4 = (2 * MAX_NODES) / 4;  // 100,000 float4s

    zero_deg_kernel<<<(NV4 + TPB - 1) / TPB, TPB>>>();

    scatter_deg_kernel<<<(n4 + TPB - 1) / TPB, TPB>>>(
        (const float4*)w, (const int4*)src, (const int4*)dst, n4);
    if (tail > 0) {
        scatter_tail_kernel<<<1, TPB>>>(w, src, dst, 4 * n4, E);
    }

    rsqrt_deg_kernel<<<(NV4 + TPB - 1) / TPB, TPB>>>();

    gather_mul_kernel<<<(n4 + G_TPB - 1) / G_TPB, G_TPB>>>(
        (const float4*)w, (const int4*)src, (const int4*)dst,
        (float4*)out, n4);
    if (tail > 0) {
        gather_tail_kernel<<<1, TPB>>>(w, src, dst, out, 4 * n4, E);
    }
}